// round 3
// baseline (speedup 1.0000x reference)
#include <cuda_runtime.h>
#include <cuda_bf16.h>
#include <cstdint>

#define NUM_USERS 100000
#define NUM_ITEMS 100000
#define N_NODES   200000
#define EMB       64
#define N_EDGES   3200000

#define SCAN_TILE 1024
#define SCAN_BLOCKS ((N_NODES + 1 + SCAN_TILE - 1) / SCAN_TILE)   // 196

// ---------------- device scratch (allocation-free rule: static globals) ----
__device__ float g_buf0[(size_t)N_NODES * EMB];   // 51.2 MB
__device__ float g_buf1[(size_t)N_NODES * EMB];   // 51.2 MB
__device__ int   g_cnt[N_NODES];
__device__ int   g_rowptr[N_NODES + 1];
__device__ int   g_cursor[N_NODES];
__device__ int2  g_edges[N_EDGES];                // (col, w-bits) interleaved
__device__ int   g_bsum [SCAN_BLOCKS + 8];
__device__ int   g_bsum2[SCAN_BLOCKS + 8];

// ---------------- helpers --------------------------------------------------
__device__ __forceinline__ int block_excl_scan_1024(int v) {
    // blockDim.x must be 1024. Returns exclusive prefix of v across the block.
    __shared__ int warp_sums[32];
    const int lane = threadIdx.x & 31;
    const int wid  = threadIdx.x >> 5;
    int incl = v;
    #pragma unroll
    for (int o = 1; o < 32; o <<= 1) {
        int n = __shfl_up_sync(0xFFFFFFFFu, incl, o);
        if (lane >= o) incl += n;
    }
    if (lane == 31) warp_sums[wid] = incl;
    __syncthreads();
    if (wid == 0) {
        int ws = warp_sums[lane];
        #pragma unroll
        for (int o = 1; o < 32; o <<= 1) {
            int n = __shfl_up_sync(0xFFFFFFFFu, ws, o);
            if (lane >= o) ws += n;
        }
        warp_sums[lane] = ws;   // inclusive warp prefix
    }
    __syncthreads();
    int warp_off = (wid > 0) ? warp_sums[wid - 1] : 0;
    return warp_off + incl - v;
}

// ---------------- CSR build -------------------------------------------------
__global__ void k_zero_cnt() {
    int i = blockIdx.x * blockDim.x + threadIdx.x;
    if (i < N_NODES) g_cnt[i] = 0;
}

__global__ void k_hist(const int* __restrict__ erow) {
    int e = blockIdx.x * blockDim.x + threadIdx.x;
    if (e < N_EDGES) atomicAdd(&g_cnt[erow[e]], 1);
}

__global__ void k_scan_blocksums() {
    int i = blockIdx.x * SCAN_TILE + threadIdx.x;
    int v = (i < N_NODES) ? g_cnt[i] : 0;
    __shared__ int sh[32];
    #pragma unroll
    for (int o = 16; o; o >>= 1) v += __shfl_down_sync(0xFFFFFFFFu, v, o);
    if ((threadIdx.x & 31) == 0) sh[threadIdx.x >> 5] = v;
    __syncthreads();
    if (threadIdx.x < 32) {
        int t = sh[threadIdx.x];
        #pragma unroll
        for (int o = 16; o; o >>= 1) t += __shfl_down_sync(0xFFFFFFFFu, t, o);
        if (threadIdx.x == 0) g_bsum[blockIdx.x] = t;
    }
}

__global__ void k_scan_sums() {
    // single block of 1024 threads; SCAN_BLOCKS <= 1024
    int v = (threadIdx.x < SCAN_BLOCKS) ? g_bsum[threadIdx.x] : 0;
    int ex = block_excl_scan_1024(v);
    if (threadIdx.x < SCAN_BLOCKS) g_bsum2[threadIdx.x] = ex;
}

__global__ void k_scan_final() {
    int i = blockIdx.x * SCAN_TILE + threadIdx.x;
    int v = (i < N_NODES) ? g_cnt[i] : 0;
    int ex = block_excl_scan_1024(v) + g_bsum2[blockIdx.x];
    if (i < N_NODES) {
        g_rowptr[i] = ex;
        g_cursor[i] = ex;
    } else if (i == N_NODES) {
        g_rowptr[N_NODES] = ex;   // v==0 here, ex == total edges
    }
}

__global__ void k_scatter(const int* __restrict__ erow,
                          const int* __restrict__ ecol,
                          const float* __restrict__ ew) {
    int e = blockIdx.x * blockDim.x + threadIdx.x;
    if (e < N_EDGES) {
        int r = erow[e];
        int p = atomicAdd(&g_cursor[r], 1);
        g_edges[p] = make_int2(ecol[e], __float_as_int(ew[e]));
    }
}

// ---------------- ego init: concat(user_emb, item_emb) into buf0 ----------
__global__ void k_concat(const float4* __restrict__ u, const float4* __restrict__ it) {
    const int half  = NUM_USERS * EMB / 4;
    const int total = N_NODES * EMB / 4;
    int i = blockIdx.x * blockDim.x + threadIdx.x;
    if (i < half)       ((float4*)g_buf0)[i] = u[i];
    else if (i < total) ((float4*)g_buf0)[i] = it[i - half];
}

// ---------------- SpMM: one warp per row, float2 per lane ------------------
// LAYER 1: buf0 -> buf1, out  = y/3   (also overwrites 0xAA poison)
// LAYER 2: buf1 -> buf0, out += y/3
// LAYER 3: buf0 -> (none), out += y/3
template <int LAYER>
__global__ void __launch_bounds__(256) k_spmm(float* __restrict__ out) {
    const int gw = (blockIdx.x * blockDim.x + threadIdx.x) >> 5;
    if (gw >= N_NODES) return;
    const int lane = threadIdx.x & 31;

    const float2* __restrict__ x2 =
        (const float2*)((LAYER == 2) ? g_buf1 : g_buf0);

    const int s = g_rowptr[gw];
    const int e = g_rowptr[gw + 1];

    float ax = 0.0f, ay = 0.0f;
    for (int base = s; base < e; base += 32) {
        int cnt = e - base; if (cnt > 32) cnt = 32;
        int2 ed = (lane < cnt) ? g_edges[base + lane] : make_int2(0, 0);
        for (int j = 0; j < cnt; j++) {
            int   c = __shfl_sync(0xFFFFFFFFu, ed.x, j);
            float w = __int_as_float(__shfl_sync(0xFFFFFFFFu, ed.y, j));
            float2 v = __ldg(&x2[c * 32 + lane]);
            ax = fmaf(w, v.x, ax);
            ay = fmaf(w, v.y, ay);
        }
    }

    const int idx = gw * 32 + lane;

    if (LAYER < 3) {
        float2* __restrict__ y2 = (float2*)((LAYER == 1) ? g_buf1 : g_buf0);
        y2[idx] = make_float2(ax, ay);
    }

    const float inv3 = 1.0f / 3.0f;
    float2* __restrict__ o2 = (float2*)out;
    if (LAYER == 1) {
        o2[idx] = make_float2(ax * inv3, ay * inv3);
    } else {
        float2 o = o2[idx];
        o.x = fmaf(ax, inv3, o.x);
        o.y = fmaf(ay, inv3, o.y);
        o2[idx] = o;
    }
}

// ---------------- launch ----------------------------------------------------
extern "C" void kernel_launch(void* const* d_in, const int* in_sizes, int n_in,
                              void* d_out, int out_size) {
    (void)in_sizes; (void)n_in; (void)out_size;
    const float* u   = (const float*)d_in[0];
    const float* it  = (const float*)d_in[1];
    const float* ew  = (const float*)d_in[2];
    const int*   er  = (const int*)d_in[3];
    const int*   ec  = (const int*)d_in[4];
    float*       out = (float*)d_out;

    // CSR build
    k_zero_cnt<<<(N_NODES + 255) / 256, 256>>>();
    k_hist<<<(N_EDGES + 255) / 256, 256>>>(er);
    k_scan_blocksums<<<SCAN_BLOCKS, SCAN_TILE>>>();
    k_scan_sums<<<1, SCAN_TILE>>>();
    k_scan_final<<<SCAN_BLOCKS, SCAN_TILE>>>();
    k_scatter<<<(N_EDGES + 255) / 256, 256>>>(er, ec, ew);

    // ego init
    k_concat<<<(N_NODES * EMB / 4 + 255) / 256, 256>>>((const float4*)u,
                                                       (const float4*)it);

    // 3 propagation layers (warp per row: 200000 warps)
    const int spmm_blocks = (N_NODES * 32 + 255) / 256;
    k_spmm<1><<<spmm_blocks, 256>>>(out);
    k_spmm<2><<<spmm_blocks, 256>>>(out);
    k_spmm<3><<<spmm_blocks, 256>>>(out);
}

// round 6
// speedup vs baseline: 1.1238x; 1.1238x over previous
#include <cuda_runtime.h>
#include <cuda_fp16.h>
#include <cuda_bf16.h>
#include <cstdint>

#define NUM_USERS 100000
#define NUM_ITEMS 100000
#define N_NODES   200000
#define EMB       64
#define N_EDGES   3200000

#define SCAN_TILE 1024
#define SCAN_BLOCKS ((N_NODES + 1 + SCAN_TILE - 1) / SCAN_TILE)   // 196

// ---------------- device scratch (allocation-free rule: static globals) ----
__device__ __half g_h0[(size_t)N_NODES * EMB];    // 25.6 MB  (fp16 x ping)
__device__ __half g_h1[(size_t)N_NODES * EMB];    // 25.6 MB  (fp16 x pong)
__device__ int    g_cnt[N_NODES];
__device__ int    g_rowptr[N_NODES + 1];
__device__ int    g_cursor[N_NODES];
__device__ int2   g_edges[N_EDGES];               // (col, w-bits) interleaved
__device__ int    g_bsum [SCAN_BLOCKS + 8];
__device__ int    g_bsum2[SCAN_BLOCKS + 8];

// ---------------- helpers --------------------------------------------------
__device__ __forceinline__ unsigned pack_half2(__half2 h) {
    return ((unsigned)__half_as_ushort(__high2half(h)) << 16) |
           (unsigned)__half_as_ushort(__low2half(h));
}

__device__ __forceinline__ int block_excl_scan_1024(int v) {
    __shared__ int warp_sums[32];
    const int lane = threadIdx.x & 31;
    const int wid  = threadIdx.x >> 5;
    int incl = v;
    #pragma unroll
    for (int o = 1; o < 32; o <<= 1) {
        int n = __shfl_up_sync(0xFFFFFFFFu, incl, o);
        if (lane >= o) incl += n;
    }
    if (lane == 31) warp_sums[wid] = incl;
    __syncthreads();
    if (wid == 0) {
        int ws = warp_sums[lane];
        #pragma unroll
        for (int o = 1; o < 32; o <<= 1) {
            int n = __shfl_up_sync(0xFFFFFFFFu, ws, o);
            if (lane >= o) ws += n;
        }
        warp_sums[lane] = ws;
    }
    __syncthreads();
    int warp_off = (wid > 0) ? warp_sums[wid - 1] : 0;
    return warp_off + incl - v;
}

// ---------------- CSR build -------------------------------------------------
__global__ void k_zero_cnt() {
    int i = blockIdx.x * blockDim.x + threadIdx.x;
    if (i < N_NODES) g_cnt[i] = 0;
}

__global__ void k_hist(const int* __restrict__ erow) {
    int e = blockIdx.x * blockDim.x + threadIdx.x;
    if (e < N_EDGES) atomicAdd(&g_cnt[erow[e]], 1);
}

__global__ void k_scan_blocksums() {
    int i = blockIdx.x * SCAN_TILE + threadIdx.x;
    int v = (i < N_NODES) ? g_cnt[i] : 0;
    __shared__ int sh[32];
    #pragma unroll
    for (int o = 16; o; o >>= 1) v += __shfl_down_sync(0xFFFFFFFFu, v, o);
    if ((threadIdx.x & 31) == 0) sh[threadIdx.x >> 5] = v;
    __syncthreads();
    if (threadIdx.x < 32) {
        int t = sh[threadIdx.x];
        #pragma unroll
        for (int o = 16; o; o >>= 1) t += __shfl_down_sync(0xFFFFFFFFu, t, o);
        if (threadIdx.x == 0) g_bsum[blockIdx.x] = t;
    }
}

__global__ void k_scan_sums() {
    int v = (threadIdx.x < SCAN_BLOCKS) ? g_bsum[threadIdx.x] : 0;
    int ex = block_excl_scan_1024(v);
    if (threadIdx.x < SCAN_BLOCKS) g_bsum2[threadIdx.x] = ex;
}

__global__ void k_scan_final() {
    int i = blockIdx.x * SCAN_TILE + threadIdx.x;
    int v = (i < N_NODES) ? g_cnt[i] : 0;
    int ex = block_excl_scan_1024(v) + g_bsum2[blockIdx.x];
    if (i < N_NODES) {
        g_rowptr[i] = ex;
        g_cursor[i] = ex;
    } else if (i == N_NODES) {
        g_rowptr[N_NODES] = ex;
    }
}

__global__ void k_scatter(const int* __restrict__ erow,
                          const int* __restrict__ ecol,
                          const float* __restrict__ ew) {
    int e = blockIdx.x * blockDim.x + threadIdx.x;
    if (e < N_EDGES) {
        int r = erow[e];
        int p = atomicAdd(&g_cursor[r], 1);
        g_edges[p] = make_int2(ecol[e], __float_as_int(ew[e]));
    }
}

// ---------------- ego init: concat + fp32 -> fp16 into g_h0 ----------------
__global__ void k_convert(const float4* __restrict__ u,
                          const float4* __restrict__ it) {
    const int half_f4  = NUM_USERS * EMB / 4;
    const int total_f4 = N_NODES * EMB / 4;
    int i = blockIdx.x * blockDim.x + threadIdx.x;
    if (i >= total_f4) return;
    float4 v = (i < half_f4) ? u[i] : it[i - half_f4];
    uint2 packed;
    packed.x = pack_half2(__floats2half2_rn(v.x, v.y));
    packed.y = pack_half2(__floats2half2_rn(v.z, v.w));
    ((uint2*)g_h0)[i] = packed;
}

// ---------------- SpMM: one warp per row, half2 gather, fp32 accumulate ----
// LAYER 1: h0 -> h1, out  = y/3   (also overwrites 0xAA poison)
// LAYER 2: h1 -> h0, out += y/3
// LAYER 3: h0 -> (none), out += y/3
template <int LAYER>
__global__ void __launch_bounds__(256) k_spmm(float* __restrict__ out) {
    const int gw = (blockIdx.x * blockDim.x + threadIdx.x) >> 5;
    if (gw >= N_NODES) return;
    const int lane = threadIdx.x & 31;

    const __half2* __restrict__ x2 =
        (const __half2*)((LAYER == 2) ? g_h1 : g_h0);

    const int s = g_rowptr[gw];
    const int e = g_rowptr[gw + 1];

    float ax = 0.0f, ay = 0.0f;
    for (int base = s; base < e; base += 32) {
        int cnt = e - base; if (cnt > 32) cnt = 32;
        int2 ed = (lane < cnt) ? g_edges[base + lane] : make_int2(0, 0);
        for (int j = 0; j < cnt; j++) {
            int   c = __shfl_sync(0xFFFFFFFFu, ed.x, j);
            float w = __int_as_float(__shfl_sync(0xFFFFFFFFu, ed.y, j));
            __half2 vh = __ldg(&x2[c * 32 + lane]);   // 128B/edge, one L2 line
            float2 v = __half22float2(vh);
            ax = fmaf(w, v.x, ax);
            ay = fmaf(w, v.y, ay);
        }
    }

    const int idx = gw * 32 + lane;

    if (LAYER < 3) {
        __half2* __restrict__ y2 = (__half2*)((LAYER == 1) ? g_h1 : g_h0);
        y2[idx] = __floats2half2_rn(ax, ay);
    }

    const float inv3 = 1.0f / 3.0f;
    float2* o2 = (float2*)out;
    if (LAYER == 1) {
        __stcs(&o2[idx], make_float2(ax * inv3, ay * inv3));
    } else {
        float2 o = __ldcs(&o2[idx]);
        o.x = fmaf(ax, inv3, o.x);
        o.y = fmaf(ay, inv3, o.y);
        __stcs(&o2[idx], o);
    }
}

// ---------------- launch ----------------------------------------------------
extern "C" void kernel_launch(void* const* d_in, const int* in_sizes, int n_in,
                              void* d_out, int out_size) {
    (void)in_sizes; (void)n_in; (void)out_size;
    const float* u   = (const float*)d_in[0];
    const float* it  = (const float*)d_in[1];
    const float* ew  = (const float*)d_in[2];
    const int*   er  = (const int*)d_in[3];
    const int*   ec  = (const int*)d_in[4];
    float*       out = (float*)d_out;

    // CSR build
    k_zero_cnt<<<(N_NODES + 255) / 256, 256>>>();
    k_hist<<<(N_EDGES + 255) / 256, 256>>>(er);
    k_scan_blocksums<<<SCAN_BLOCKS, SCAN_TILE>>>();
    k_scan_sums<<<1, SCAN_TILE>>>();
    k_scan_final<<<SCAN_BLOCKS, SCAN_TILE>>>();
    k_scatter<<<(N_EDGES + 255) / 256, 256>>>(er, ec, ew);

    // ego init (concat + fp16 convert fused)
    k_convert<<<(N_NODES * EMB / 4 + 255) / 256, 256>>>((const float4*)u,
                                                        (const float4*)it);

    // 3 propagation layers
    const int spmm_blocks = (N_NODES * 32 + 255) / 256;
    k_spmm<1><<<spmm_blocks, 256>>>(out);
    k_spmm<2><<<spmm_blocks, 256>>>(out);
    k_spmm<3><<<spmm_blocks, 256>>>(out);
}

// round 10
// speedup vs baseline: 1.3421x; 1.1942x over previous
#include <cuda_runtime.h>
#include <cuda_fp16.h>
#include <cuda_bf16.h>
#include <cstdint>

#define NUM_USERS 100000
#define NUM_ITEMS 100000
#define N_NODES   200000
#define EMB       64
#define N_EDGES   3200000

#define SCAN_TILE 1024
#define SCAN_BLOCKS ((N_NODES + 1 + SCAN_TILE - 1) / SCAN_TILE)   // 196

// ---------------- device scratch (allocation-free rule: static globals) ----
__device__ __half g_h0[(size_t)N_NODES * EMB];    // 25.6 MB  (x0, then y2)
__device__ __half g_h1[(size_t)N_NODES * EMB];    // 25.6 MB  (y1)
__device__ int    g_cnt[N_NODES];
__device__ int    g_rowptr[N_NODES + 1];
__device__ int    g_cursor[N_NODES];
__device__ int2   g_edges[N_EDGES];               // (col, w-bits) interleaved
__device__ int    g_bsum [SCAN_BLOCKS + 8];
__device__ int    g_bsum2[SCAN_BLOCKS + 8];

// ---------------- helpers --------------------------------------------------
__device__ __forceinline__ unsigned pack_half2(__half2 h) {
    return ((unsigned)__half_as_ushort(__high2half(h)) << 16) |
           (unsigned)__half_as_ushort(__low2half(h));
}

__device__ __forceinline__ float2 unpack_h2(unsigned u) {
    __half2 h;
    *(unsigned*)&h = u;
    return __half22float2(h);
}

__device__ __forceinline__ int block_excl_scan_1024(int v) {
    __shared__ int warp_sums[32];
    const int lane = threadIdx.x & 31;
    const int wid  = threadIdx.x >> 5;
    int incl = v;
    #pragma unroll
    for (int o = 1; o < 32; o <<= 1) {
        int n = __shfl_up_sync(0xFFFFFFFFu, incl, o);
        if (lane >= o) incl += n;
    }
    if (lane == 31) warp_sums[wid] = incl;
    __syncthreads();
    if (wid == 0) {
        int ws = warp_sums[lane];
        #pragma unroll
        for (int o = 1; o < 32; o <<= 1) {
            int n = __shfl_up_sync(0xFFFFFFFFu, ws, o);
            if (lane >= o) ws += n;
        }
        warp_sums[lane] = ws;
    }
    __syncthreads();
    int warp_off = (wid > 0) ? warp_sums[wid - 1] : 0;
    return warp_off + incl - v;
}

// ---------------- ego init: concat + fp32->fp16 into g_h0; zero g_cnt ------
__global__ void k_convert(const float4* __restrict__ u,
                          const float4* __restrict__ it) {
    const int half_f4  = NUM_USERS * EMB / 4;
    const int total_f4 = N_NODES * EMB / 4;
    int i = blockIdx.x * blockDim.x + threadIdx.x;
    if (i < N_NODES) g_cnt[i] = 0;          // fused zero of histogram
    if (i >= total_f4) return;
    float4 v = (i < half_f4) ? u[i] : it[i - half_f4];
    uint2 packed;
    packed.x = pack_half2(__floats2half2_rn(v.x, v.y));
    packed.y = pack_half2(__floats2half2_rn(v.z, v.w));
    ((uint2*)g_h0)[i] = packed;
}

// ---------------- CSR build -------------------------------------------------
__global__ void k_hist(const int* __restrict__ erow) {
    int e = blockIdx.x * blockDim.x + threadIdx.x;
    if (e < N_EDGES) atomicAdd(&g_cnt[erow[e]], 1);
}

__global__ void k_scan_blocksums() {
    int i = blockIdx.x * SCAN_TILE + threadIdx.x;
    int v = (i < N_NODES) ? g_cnt[i] : 0;
    __shared__ int sh[32];
    #pragma unroll
    for (int o = 16; o; o >>= 1) v += __shfl_down_sync(0xFFFFFFFFu, v, o);
    if ((threadIdx.x & 31) == 0) sh[threadIdx.x >> 5] = v;
    __syncthreads();
    if (threadIdx.x < 32) {
        int t = sh[threadIdx.x];
        #pragma unroll
        for (int o = 16; o; o >>= 1) t += __shfl_down_sync(0xFFFFFFFFu, t, o);
        if (threadIdx.x == 0) g_bsum[blockIdx.x] = t;
    }
}

__global__ void k_scan_sums() {
    int v = (threadIdx.x < SCAN_BLOCKS) ? g_bsum[threadIdx.x] : 0;
    int ex = block_excl_scan_1024(v);
    if (threadIdx.x < SCAN_BLOCKS) g_bsum2[threadIdx.x] = ex;
}

__global__ void k_scan_final() {
    int i = blockIdx.x * SCAN_TILE + threadIdx.x;
    int v = (i < N_NODES) ? g_cnt[i] : 0;
    int ex = block_excl_scan_1024(v) + g_bsum2[blockIdx.x];
    if (i < N_NODES) {
        g_rowptr[i] = ex;
        g_cursor[i] = ex;
    } else if (i == N_NODES) {
        g_rowptr[N_NODES] = ex;
    }
}

__global__ void k_scatter(const int* __restrict__ erow,
                          const int* __restrict__ ecol,
                          const float* __restrict__ ew) {
    int e = blockIdx.x * blockDim.x + threadIdx.x;
    if (e < N_EDGES) {
        int r = erow[e];
        int p = atomicAdd(&g_cursor[r], 1);
        g_edges[p] = make_int2(ecol[e], __float_as_int(ew[e]));
    }
}

// ---------------- SpMM: one warp per row, 16 lanes per edge ----------------
// Each lane loads uint2 = 4 fp16 embs (8B); 16 lanes cover one 128B row.
// The warp processes 2 edges per iteration (half-warps 0/1).
// LAYER 1: gather h0 -> write y1 to h1
// LAYER 2: gather h1 -> write y2 to h0
// LAYER 3: gather h0 -> out = (h1[row] + h0[row] + y3) / 3
template <int LAYER>
__global__ void __launch_bounds__(256) k_spmm(float* __restrict__ out) {
    const int gw = (blockIdx.x * blockDim.x + threadIdx.x) >> 5;
    if (gw >= N_NODES) return;
    const int lane = threadIdx.x & 31;
    const int half = lane >> 4;     // which edge of the pair
    const int hl   = lane & 15;     // emb-chunk index (4 embs per lane)

    const uint2* __restrict__ x4 =
        (const uint2*)((LAYER == 2) ? g_h1 : g_h0);

    const int s = g_rowptr[gw];
    const int e = g_rowptr[gw + 1];

    float a0 = 0.f, a1 = 0.f, a2 = 0.f, a3 = 0.f;

    for (int base = s; base < e; base += 32) {
        int cnt = e - base; if (cnt > 32) cnt = 32;
        int2 ed = (lane < cnt) ? __ldg(&g_edges[base + lane]) : make_int2(0, 0);
        int iters = (cnt + 1) >> 1;
        for (int t = 0; t < iters; t++) {
            int src = 2 * t + half;
            int c  = __shfl_sync(0xFFFFFFFFu, ed.x, src);
            int wb = __shfl_sync(0xFFFFFFFFu, ed.y, src);
            float w = (src < cnt) ? __int_as_float(wb) : 0.0f;
            uint2 v = __ldg(&x4[c * 16 + hl]);      // 4 embs of row c
            float2 p = unpack_h2(v.x);
            float2 q = unpack_h2(v.y);
            a0 = fmaf(w, p.x, a0);
            a1 = fmaf(w, p.y, a1);
            a2 = fmaf(w, q.x, a2);
            a3 = fmaf(w, q.y, a3);
        }
    }

    // combine the two half-warp partial sums (lane L and L^16 share emb dims)
    a0 += __shfl_xor_sync(0xFFFFFFFFu, a0, 16);
    a1 += __shfl_xor_sync(0xFFFFFFFFu, a1, 16);
    a2 += __shfl_xor_sync(0xFFFFFFFFu, a2, 16);
    a3 += __shfl_xor_sync(0xFFFFFFFFu, a3, 16);

    const int rb = gw * 16;   // row base in uint2 / float4 units

    if (LAYER < 3) {
        if (half == 0) {
            uint2 st;
            st.x = pack_half2(__floats2half2_rn(a0, a1));
            st.y = pack_half2(__floats2half2_rn(a2, a3));
            ((uint2*)((LAYER == 1) ? g_h1 : g_h0))[rb + hl] = st;
        }
    } else {
        if (half == 0) {
            uint2 v1 = ((const uint2*)g_h1)[rb + hl];   // y1 (own row)
            uint2 v2 = ((const uint2*)g_h0)[rb + hl];   // y2 (own row)
            float2 p1 = unpack_h2(v1.x), q1 = unpack_h2(v1.y);
            float2 p2 = unpack_h2(v2.x), q2 = unpack_h2(v2.y);
            const float inv3 = 1.0f / 3.0f;
            float4 r;
            r.x = (p1.x + p2.x + a0) * inv3;
            r.y = (p1.y + p2.y + a1) * inv3;
            r.z = (q1.x + q2.x + a2) * inv3;
            r.w = (q1.y + q2.y + a3) * inv3;
            __stcs(&((float4*)out)[rb + hl], r);
        }
    }
}

// ---------------- launch ----------------------------------------------------
extern "C" void kernel_launch(void* const* d_in, const int* in_sizes, int n_in,
                              void* d_out, int out_size) {
    (void)in_sizes; (void)n_in; (void)out_size;
    const float* u   = (const float*)d_in[0];
    const float* it  = (const float*)d_in[1];
    const float* ew  = (const float*)d_in[2];
    const int*   er  = (const int*)d_in[3];
    const int*   ec  = (const int*)d_in[4];
    float*       out = (float*)d_out;

    // ego init (concat + fp16 convert) fused with histogram zeroing
    k_convert<<<(N_NODES * EMB / 4 + 255) / 256, 256>>>((const float4*)u,
                                                        (const float4*)it);
    // CSR build
    k_hist<<<(N_EDGES + 255) / 256, 256>>>(er);
    k_scan_blocksums<<<SCAN_BLOCKS, SCAN_TILE>>>();
    k_scan_sums<<<1, SCAN_TILE>>>();
    k_scan_final<<<SCAN_BLOCKS, SCAN_TILE>>>();
    k_scatter<<<(N_EDGES + 255) / 256, 256>>>(er, ec, ew);

    // 3 propagation layers (one warp per row)
    const int spmm_blocks = (N_NODES * 32 + 255) / 256;
    k_spmm<1><<<spmm_blocks, 256>>>(out);
    k_spmm<2><<<spmm_blocks, 256>>>(out);
    k_spmm<3><<<spmm_blocks, 256>>>(out);
}